// round 8
// baseline (speedup 1.0000x reference)
#include <cuda_runtime.h>
#include <math.h>

// Problem constants (fixed by setup_inputs): bs=16, C=256, H=W=128
#define BS 16
#define CC 256
#define NN 16384           // H*W
#define WORDS_PER_B 512    // NN / 32
#define TOPK 12

// ---------------- scratch (device globals; no allocation allowed) ----------
__device__ unsigned g_mask[2][BS][WORDS_PER_B];  // [side][b][word], side 0=fg, 1=bg
__device__ int      g_cnt[2][BS];
__device__ int      g_flagbad[BS];               // !=0 if fg/bg masks not exact complements
__device__ int      g_topk_idx[2][BS][TOPK];
__device__ float    g_sum_fg[BS][CC];
__device__ float    g_sum_bg[BS][CC];

// ---------------------------------------------------------------------------
// Kernel 1: build fg/bg bitmasks + counts + complement flag.
// grid = 16 (one block per b), block = 512 (16 warps, each warp owns 1024 n)
// ---------------------------------------------------------------------------
__global__ void __launch_bounds__(512) mask_kernel(const float* __restrict__ outp,
                                                   const float* __restrict__ tau_p) {
    const int b    = blockIdx.x;
    const int t    = threadIdx.x;
    const int warp = t >> 5;
    const int lane = t & 31;

    const float tau = *tau_p;
    const float Tf  = 1.0f / (1.0f + expf(-tau));   // sigmoid(tau)
    const float Tb  = 1.0f - Tf;

    const float* o0 = outp + (size_t)b * (2 * NN);
    const float* o1 = o0 + NN;

    int cf = 0, cb = 0, bad = 0;
    #pragma unroll 4
    for (int j = 0; j < 32; j++) {
        const int n = warp * 1024 + j * 32 + lane;  // coalesced within warp
        const float a  = o0[n];
        const float b1 = o1[n];
        const float m  = fmaxf(a, b1);
        const float e0 = expf(a - m);
        const float e1 = expf(b1 - m);
        const float s  = e0 + e1;
        const float pf = e1 / s;                    // softmax channel 1 (fg)
        const float pb = e0 / s;                    // softmax channel 0 (bg)
        const unsigned wf = __ballot_sync(0xffffffffu, pf > Tf);
        const unsigned wb = __ballot_sync(0xffffffffu, pb > Tb);
        if (lane == 0) {
            g_mask[0][b][warp * 32 + j] = wf;
            g_mask[1][b][warp * 32 + j] = wb;
            cf  += __popc(wf);
            cb  += __popc(wb);
            bad += ((wf ^ wb) != 0xffffffffu) ? 1 : 0;
        }
    }

    __shared__ int rf[16], rb[16], rbad[16];
    if (lane == 0) { rf[warp] = cf; rb[warp] = cb; rbad[warp] = bad; }
    __syncthreads();
    if (t == 0) {
        int a = 0, bb = 0, bd = 0;
        #pragma unroll
        for (int w = 0; w < 16; w++) { a += rf[w]; bb += rb[w]; bd += rbad[w]; }
        g_cnt[0][b]   = a;
        g_cnt[1][b]   = bb;
        g_flagbad[b]  = bd;
    }
}

// ---------------------------------------------------------------------------
// Kernel 2: exact top-12 indices of pred (per b, per side). Only runs if
// cnt==0 for that (side,b) — essentially never with this data, but exact.
// Tie-break matches jax.lax.top_k: descending value, ascending index.
// grid = (16, 2), block = 256
// ---------------------------------------------------------------------------
__global__ void __launch_bounds__(256) topk_kernel(const float* __restrict__ outp) {
    const int b    = blockIdx.x;
    const int side = blockIdx.y;
    if (g_cnt[side][b] > 0) return;   // uniform early exit (hot case)

    const int t = threadIdx.x;
    const float* o0 = outp + (size_t)b * (2 * NN);
    const float* o1 = o0 + NN;

    float v[TOPK];
    int   ix[TOPK];
    #pragma unroll
    for (int k = 0; k < TOPK; k++) { v[k] = -INFINITY; ix[k] = 0x7fffffff; }

    for (int j = t; j < NN; j += 256) {
        const float a  = o0[j];
        const float b1 = o1[j];
        const float m  = fmaxf(a, b1);
        const float e0 = expf(a - m);
        const float e1 = expf(b1 - m);
        const float s  = e0 + e1;
        const float p  = (side == 0) ? (e1 / s) : (e0 / s);
        // insert (p, j) if it beats the worst entry
        if ((p > v[TOPK - 1]) || (p == v[TOPK - 1] && j < ix[TOPK - 1])) {
            int k = TOPK - 1;
            while (k > 0 && ((p > v[k - 1]) || (p == v[k - 1] && j < ix[k - 1]))) {
                v[k] = v[k - 1]; ix[k] = ix[k - 1]; k--;
            }
            v[k] = p; ix[k] = j;
        }
    }

    __shared__ float sv[256 * TOPK];
    __shared__ int   si[256 * TOPK];
    #pragma unroll
    for (int k = 0; k < TOPK; k++) { sv[t * TOPK + k] = v[k]; si[t * TOPK + k] = ix[k]; }
    __syncthreads();

    for (int stride = 128; stride > 0; stride >>= 1) {
        if (t < stride) {
            float* A  = &sv[t * TOPK];
            int*   Ai = &si[t * TOPK];
            float* B  = &sv[(t + stride) * TOPK];
            int*   Bi = &si[(t + stride) * TOPK];
            float mv[TOPK]; int mi[TOPK];
            int i = 0, j = 0;
            #pragma unroll
            for (int o = 0; o < TOPK; o++) {
                const float av = A[i], bv = B[j];
                const int aix = Ai[i], bix = Bi[j];
                const bool takeA = (av > bv) || (av == bv && aix <= bix);
                if (takeA) { mv[o] = av; mi[o] = aix; i++; }
                else       { mv[o] = bv; mi[o] = bix; j++; }
            }
            #pragma unroll
            for (int o = 0; o < TOPK; o++) { A[o] = mv[o]; Ai[o] = mi[o]; }
        }
        __syncthreads();
    }
    if (t == 0) {
        #pragma unroll
        for (int k = 0; k < TOPK; k++) g_topk_idx[side][b][k] = si[k];
    }
}

// ---------------------------------------------------------------------------
// Kernel 3: the 268 MB streaming pass. One block per (b,c) row (grid 256x16).
// Fast path (masks are complements): accumulate total and fg; bg = tot - fg.
// Slow path (threshold tie somewhere in batch b): accumulate fg and bg directly.
// ---------------------------------------------------------------------------
__global__ void __launch_bounds__(256) sum_kernel(const float* __restrict__ feat) {
    __shared__ unsigned s_fg[WORDS_PER_B];
    __shared__ unsigned s_bg[WORDS_PER_B];
    __shared__ float    red[3][8];

    const int t = threadIdx.x;
    const int c = blockIdx.x;
    const int b = blockIdx.y;

    // stage masks for this b into smem (2 KB each)
    s_fg[t]       = g_mask[0][b][t];
    s_fg[t + 256] = g_mask[0][b][t + 256];
    s_bg[t]       = g_mask[1][b][t];
    s_bg[t + 256] = g_mask[1][b][t + 256];
    const bool bad = (g_flagbad[b] != 0);
    __syncthreads();

    const float4* row = (const float4*)(feat + (((size_t)b * CC + c) << 14));
    // element n = (i*256 + t)*4  ->  word = i*32 + (t>>3), shift = (t&7)*4 (constant)
    const int widx0 = t >> 3;
    const int sh    = (t & 7) * 4;

    float tot = 0.0f, fg = 0.0f, bg = 0.0f;

    if (!bad) {
        #pragma unroll
        for (int i = 0; i < 16; i++) {
            const float4 f = row[i * 256 + t];
            const unsigned bits = s_fg[i * 32 + widx0] >> sh;
            tot += (f.x + f.y) + (f.z + f.w);
            if (bits & 1u) fg += f.x;
            if (bits & 2u) fg += f.y;
            if (bits & 4u) fg += f.z;
            if (bits & 8u) fg += f.w;
        }
    } else {
        #pragma unroll
        for (int i = 0; i < 16; i++) {
            const float4 f = row[i * 256 + t];
            const unsigned bf = s_fg[i * 32 + widx0] >> sh;
            const unsigned bb = s_bg[i * 32 + widx0] >> sh;
            if (bf & 1u) fg += f.x;
            if (bf & 2u) fg += f.y;
            if (bf & 4u) fg += f.z;
            if (bf & 8u) fg += f.w;
            if (bb & 1u) bg += f.x;
            if (bb & 2u) bg += f.y;
            if (bb & 4u) bg += f.z;
            if (bb & 8u) bg += f.w;
        }
    }

    // block reduction (tot, fg, bg)
    #pragma unroll
    for (int o = 16; o > 0; o >>= 1) {
        tot += __shfl_down_sync(0xffffffffu, tot, o);
        fg  += __shfl_down_sync(0xffffffffu, fg,  o);
        bg  += __shfl_down_sync(0xffffffffu, bg,  o);
    }
    const int warp = t >> 5, lane = t & 31;
    if (lane == 0) { red[0][warp] = tot; red[1][warp] = fg; red[2][warp] = bg; }
    __syncthreads();
    if (t == 0) {
        float T = 0.0f, F = 0.0f, Bsum = 0.0f;
        #pragma unroll
        for (int w = 0; w < 8; w++) { T += red[0][w]; F += red[1][w]; Bsum += red[2][w]; }
        g_sum_fg[b][c] = F;
        g_sum_bg[b][c] = bad ? Bsum : (T - F);
    }
}

// ---------------------------------------------------------------------------
// Kernel 4: combine -> output. out[0:4096] = fg_proto, out[4096:8192] = bg_proto.
// grid = 32, block = 256
// ---------------------------------------------------------------------------
__global__ void __launch_bounds__(256) combine_kernel(const float* __restrict__ feat,
                                                      float* __restrict__ outp) {
    const int gid  = blockIdx.x * 256 + threadIdx.x;   // 0..8191
    const int side = gid >> 12;
    const int b    = (gid >> 8) & 15;
    const int c    = gid & 255;

    const int cnt = g_cnt[side][b];
    float val;
    if (cnt > 0) {
        const float s = side ? g_sum_bg[b][c] : g_sum_fg[b][c];
        val = s / (float)cnt;
    } else {
        const float* row = feat + (((size_t)b * CC + c) << 14);
        float s = 0.0f;
        #pragma unroll
        for (int k = 0; k < TOPK; k++) s += row[g_topk_idx[side][b][k]];
        val = s / 12.0f;
    }
    outp[gid] = val;
}

// ---------------------------------------------------------------------------
extern "C" void kernel_launch(void* const* d_in, const int* in_sizes, int n_in,
                              void* d_out, int out_size) {
    (void)in_sizes; (void)n_in; (void)out_size;
    const float* feat = (const float*)d_in[0];   // (16,256,128,128) f32
    const float* outv = (const float*)d_in[1];   // (16,2,128,128)   f32
    const float* tau  = (const float*)d_in[2];   // scalar f32
    float* outp = (float*)d_out;                 // 8192 f32: fg(4096) ++ bg(4096)

    mask_kernel<<<BS, 512>>>(outv, tau);
    topk_kernel<<<dim3(BS, 2), 256>>>(outv);
    sum_kernel<<<dim3(CC, BS), 256>>>(feat);
    combine_kernel<<<32, 256>>>(feat, outp);
}